// round 1
// baseline (speedup 1.0000x reference)
#include <cuda_runtime.h>
#include <cuda_bf16.h>

// Problem constants (fixed by the reference setup_inputs)
constexpr int N_USERS = 200000;
constexpr int N_ITEMS = 100000;
constexpr int N_NODES = N_USERS + N_ITEMS;   // 300000
constexpr int DV      = 16;                  // 64 floats = 16 float4 per row
constexpr int N_EDGES = 2000000;
constexpr int N_IDX   = 16384;

// Ping-pong scratch: 2 x 76.8 MB device globals (allocation-free)
__device__ float4 g_bufA[(size_t)N_NODES * DV];
__device__ float4 g_bufB[(size_t)N_NODES * DV];

// Layer-0 init: A = concat(user_w, item_w); B = 0 (target of first SpMM)
__global__ void init_kernel(const float4* __restrict__ uw,
                            const float4* __restrict__ iw) {
    int t = blockIdx.x * blockDim.x + threadIdx.x;
    if (t >= N_NODES * DV) return;
    g_bufA[t] = (t < N_USERS * DV) ? __ldg(uw + t) : __ldg(iw + (t - N_USERS * DV));
    g_bufB[t] = make_float4(0.f, 0.f, 0.f, 0.f);
}

// Zero one buffer (prepare as next SpMM target). W=0 -> A, W=1 -> B.
template <int W>
__global__ void zero_kernel() {
    int t = blockIdx.x * blockDim.x + threadIdx.x;
    if (t >= N_NODES * DV) return;
    (W ? g_bufB : g_bufA)[t] = make_float4(0.f, 0.f, 0.f, 0.f);
}

// COO SpMM with vectorized global reductions.
// DIR=0: cur=A, next=B.  DIR=1: cur=B, next=A.
// 16 threads per edge; each handles one float4 component of the 256B row.
// A warp services 2 edges -> two fully-coalesced 256B row reads per LDG.
template <int DIR>
__global__ void spmm_kernel(const float* __restrict__ vals,
                            const int*   __restrict__ rows,
                            const int*   __restrict__ cols) {
    unsigned t = blockIdx.x * blockDim.x + threadIdx.x;
    unsigned e = t >> 4;
    unsigned c = t & 15u;
    if (e >= (unsigned)N_EDGES) return;

    const float4* __restrict__ cur = DIR ? g_bufB : g_bufA;
    float4*       __restrict__ nxt = DIR ? g_bufA : g_bufB;

    float v   = __ldg(vals + e);
    int   col = __ldg(cols + e);
    int   r   = __ldg(rows + e);

    float4 x = __ldg(cur + (unsigned)col * DV + c);
    float4* dst = nxt + (unsigned)r * DV + c;

    // sm_90+ vectorized fire-and-forget reduction: 1 op moves 16B
    asm volatile("red.global.add.v4.f32 [%0], {%1, %2, %3, %4};"
                 :: "l"(dst),
                    "f"(v * x.x), "f"(v * x.y), "f"(v * x.z), "f"(v * x.w)
                 : "memory");
}

// Accumulate 0.25 * buf[sampled rows] into the output (fuses mean + index).
// Output layout: user_emb (16384 x 64) followed by item_emb (16384 x 64).
// W selects which buffer holds the current layer result.
template <int W>
__global__ void gather_kernel(const int* __restrict__ uidx,
                              const int* __restrict__ iidx,
                              float4* __restrict__ out,
                              int overwrite) {
    int t = blockIdx.x * blockDim.x + threadIdx.x;
    if (t >= 2 * N_IDX * DV) return;
    int row = t >> 4;
    int c   = t & 15;
    int node = (row < N_IDX) ? __ldg(uidx + row)
                             : (N_USERS + __ldg(iidx + (row - N_IDX)));
    const float4* __restrict__ buf = W ? g_bufB : g_bufA;
    float4 x = __ldg(buf + (unsigned)node * DV + c);
    float4 o = make_float4(0.25f * x.x, 0.25f * x.y, 0.25f * x.z, 0.25f * x.w);
    if (!overwrite) {
        float4 p = out[t];
        o.x += p.x; o.y += p.y; o.z += p.z; o.w += p.w;
    }
    out[t] = o;
}

extern "C" void kernel_launch(void* const* d_in, const int* in_sizes, int n_in,
                              void* d_out, int out_size) {
    const float4* uw   = (const float4*)d_in[0];  // user_embeddings_weight (200000*64 f32)
    const float4* iw   = (const float4*)d_in[1];  // item_embeddings_weight (100000*64 f32)
    const float*  vals = (const float*)d_in[2];   // adj_vals (2M f32)
    const int*    rows = (const int*)d_in[3];     // adj_rows (2M i32)
    const int*    cols = (const int*)d_in[4];     // adj_cols (2M i32)
    const int*    uidx = (const int*)d_in[5];     // user_indices (16384 i32)
    const int*    iidx = (const int*)d_in[6];     // item_indices (16384 i32)
    float4*       out  = (float4*)d_out;          // (2*16384*64 f32)

    const int B = 256;
    const int nodeGrid   = (N_NODES * DV + B - 1) / B;
    const int spmmGrid   = (int)(((long)N_EDGES * 16 + B - 1) / B);
    const int gatherGrid = (2 * N_IDX * DV + B - 1) / B;

    // layer 0
    init_kernel<<<nodeGrid, B>>>(uw, iw);
    gather_kernel<0><<<gatherGrid, B>>>(uidx, iidx, out, 1);

    // layer 1: A -> B
    spmm_kernel<0><<<spmmGrid, B>>>(vals, rows, cols);
    gather_kernel<1><<<gatherGrid, B>>>(uidx, iidx, out, 0);
    zero_kernel<0><<<nodeGrid, B>>>();

    // layer 2: B -> A
    spmm_kernel<1><<<spmmGrid, B>>>(vals, rows, cols);
    gather_kernel<0><<<gatherGrid, B>>>(uidx, iidx, out, 0);
    zero_kernel<1><<<nodeGrid, B>>>();

    // layer 3: A -> B
    spmm_kernel<0><<<spmmGrid, B>>>(vals, rows, cols);
    gather_kernel<1><<<gatherGrid, B>>>(uidx, iidx, out, 0);
}

// round 2
// speedup vs baseline: 1.4780x; 1.4780x over previous
#include <cuda_runtime.h>
#include <cuda_bf16.h>

// Problem constants (fixed by the reference setup_inputs)
constexpr int N_USERS = 200000;
constexpr int N_ITEMS = 100000;
constexpr int N_NODES = N_USERS + N_ITEMS;   // 300000
constexpr int DV      = 16;                  // 64 floats = 16 float4 per row
constexpr int N_EDGES = 2000000;
constexpr int N_IDX   = 16384;

constexpr int SCAN_B  = 1024;
constexpr int NBLK    = (N_NODES + SCAN_B - 1) / SCAN_B;  // 293

// Allocation-free scratch (__device__ globals)
__device__ float4 g_bufA[(size_t)N_NODES * DV];   // 76.8 MB
__device__ float4 g_bufB[(size_t)N_NODES * DV];   // 76.8 MB
__device__ int    g_cnt[N_NODES];
__device__ int    g_rowptr[N_NODES + 1];
__device__ int    g_cursor[N_NODES];
__device__ int    g_bsum[NBLK];
__device__ float2 g_edge[N_EDGES];                // {val, col-as-float-bits}, row-sorted

// ---------------------------------------------------------------------------
// init: A = concat(user_w, item_w); zero the histogram counters
__global__ void init_kernel(const float4* __restrict__ uw,
                            const float4* __restrict__ iw) {
    int t = blockIdx.x * blockDim.x + threadIdx.x;
    if (t < N_NODES) g_cnt[t] = 0;
    if (t >= N_NODES * DV) return;
    g_bufA[t] = (t < N_USERS * DV) ? __ldg(uw + t) : __ldg(iw + (t - N_USERS * DV));
}

// histogram of edge rows
__global__ void hist_kernel(const int* __restrict__ rows) {
    int e = blockIdx.x * blockDim.x + threadIdx.x;
    if (e >= N_EDGES) return;
    atomicAdd(&g_cnt[__ldg(rows + e)], 1);
}

// 3-kernel exclusive scan over g_cnt -> g_rowptr (+ g_cursor copy)
__global__ void scan_blocks_kernel() {
    __shared__ int s[SCAN_B];
    int i = blockIdx.x * SCAN_B + threadIdx.x;
    int v = (i < N_NODES) ? g_cnt[i] : 0;
    s[threadIdx.x] = v;
    __syncthreads();
    #pragma unroll
    for (int off = 1; off < SCAN_B; off <<= 1) {
        int add = (threadIdx.x >= off) ? s[threadIdx.x - off] : 0;
        __syncthreads();
        s[threadIdx.x] += add;
        __syncthreads();
    }
    if (i < N_NODES) g_rowptr[i] = s[threadIdx.x] - v;      // exclusive within block
    if (threadIdx.x == SCAN_B - 1) g_bsum[blockIdx.x] = s[threadIdx.x];
}

__global__ void scan_bsums_kernel() {
    __shared__ int s[512];
    int v = (threadIdx.x < NBLK) ? g_bsum[threadIdx.x] : 0;
    s[threadIdx.x] = v;
    __syncthreads();
    #pragma unroll
    for (int off = 1; off < 512; off <<= 1) {
        int add = (threadIdx.x >= off) ? s[threadIdx.x - off] : 0;
        __syncthreads();
        s[threadIdx.x] += add;
        __syncthreads();
    }
    if (threadIdx.x < NBLK) g_bsum[threadIdx.x] = s[threadIdx.x] - v;  // exclusive
}

__global__ void scan_add_kernel() {
    int i = blockIdx.x * SCAN_B + threadIdx.x;
    if (i < N_NODES) {
        int r = g_rowptr[i] + g_bsum[blockIdx.x];
        g_rowptr[i] = r;
        g_cursor[i] = r;
    }
    if (i == 0) g_rowptr[N_NODES] = N_EDGES;
}

// scatter edges into row-sorted packed array
__global__ void scatter_kernel(const float* __restrict__ vals,
                               const int*   __restrict__ rows,
                               const int*   __restrict__ cols) {
    int e = blockIdx.x * blockDim.x + threadIdx.x;
    if (e >= N_EDGES) return;
    int r   = __ldg(rows + e);
    int pos = atomicAdd(&g_cursor[r], 1);
    g_edge[pos] = make_float2(__ldg(vals + e), __int_as_float(__ldg(cols + e)));
}

// ---------------------------------------------------------------------------
// CSR SpMM: 16 threads per row, register accumulation, single row write.
// DIR=0: cur=A, next=B.  DIR=1: cur=B, next=A.
template <int DIR>
__global__ void spmm_csr_kernel() {
    int t   = blockIdx.x * blockDim.x + threadIdx.x;
    int row = t >> 4;
    int c   = t & 15;
    if (row >= N_NODES) return;

    const float4* __restrict__ cur = DIR ? g_bufB : g_bufA;
    float4*       __restrict__ nxt = DIR ? g_bufA : g_bufB;

    int beg = __ldg(&g_rowptr[row]);
    int end = __ldg(&g_rowptr[row + 1]);

    float4 acc = make_float4(0.f, 0.f, 0.f, 0.f);
    int i = beg;
    // unroll-by-2 for extra memory-level parallelism
    for (; i + 1 < end; i += 2) {
        float2 ev0 = g_edge[i];
        float2 ev1 = g_edge[i + 1];
        float4 x0 = __ldg(cur + (unsigned)__float_as_int(ev0.y) * DV + c);
        float4 x1 = __ldg(cur + (unsigned)__float_as_int(ev1.y) * DV + c);
        acc.x += ev0.x * x0.x; acc.y += ev0.x * x0.y;
        acc.z += ev0.x * x0.z; acc.w += ev0.x * x0.w;
        acc.x += ev1.x * x1.x; acc.y += ev1.x * x1.y;
        acc.z += ev1.x * x1.z; acc.w += ev1.x * x1.w;
    }
    if (i < end) {
        float2 ev = g_edge[i];
        float4 x = __ldg(cur + (unsigned)__float_as_int(ev.y) * DV + c);
        acc.x += ev.x * x.x; acc.y += ev.x * x.y;
        acc.z += ev.x * x.z; acc.w += ev.x * x.w;
    }
    nxt[(unsigned)row * DV + c] = acc;
}

// Accumulate 0.25 * buf[sampled rows] into the output (fuses mean + index).
template <int W>
__global__ void gather_kernel(const int* __restrict__ uidx,
                              const int* __restrict__ iidx,
                              float4* __restrict__ out,
                              int overwrite) {
    int t = blockIdx.x * blockDim.x + threadIdx.x;
    if (t >= 2 * N_IDX * DV) return;
    int row = t >> 4;
    int c   = t & 15;
    int node = (row < N_IDX) ? __ldg(uidx + row)
                             : (N_USERS + __ldg(iidx + (row - N_IDX)));
    const float4* __restrict__ buf = W ? g_bufB : g_bufA;
    float4 x = __ldg(buf + (unsigned)node * DV + c);
    float4 o = make_float4(0.25f * x.x, 0.25f * x.y, 0.25f * x.z, 0.25f * x.w);
    if (!overwrite) {
        float4 p = out[t];
        o.x += p.x; o.y += p.y; o.z += p.z; o.w += p.w;
    }
    out[t] = o;
}

extern "C" void kernel_launch(void* const* d_in, const int* in_sizes, int n_in,
                              void* d_out, int out_size) {
    const float4* uw   = (const float4*)d_in[0];
    const float4* iw   = (const float4*)d_in[1];
    const float*  vals = (const float*)d_in[2];
    const int*    rows = (const int*)d_in[3];
    const int*    cols = (const int*)d_in[4];
    const int*    uidx = (const int*)d_in[5];
    const int*    iidx = (const int*)d_in[6];
    float4*       out  = (float4*)d_out;

    const int B = 256;
    const int nodeGrid   = (N_NODES * DV + B - 1) / B;      // 18750
    const int edgeGrid   = (N_EDGES + B - 1) / B;           // 7813
    const int gatherGrid = (2 * N_IDX * DV + B - 1) / B;    // 2048

    // layer 0 + CSR build
    init_kernel<<<nodeGrid, B>>>(uw, iw);
    hist_kernel<<<edgeGrid, B>>>(rows);
    gather_kernel<0><<<gatherGrid, B>>>(uidx, iidx, out, 1);
    scan_blocks_kernel<<<NBLK, SCAN_B>>>();
    scan_bsums_kernel<<<1, 512>>>();
    scan_add_kernel<<<NBLK, SCAN_B>>>();
    scatter_kernel<<<edgeGrid, B>>>(vals, rows, cols);

    // layer 1: A -> B
    spmm_csr_kernel<0><<<nodeGrid, B>>>();
    gather_kernel<1><<<gatherGrid, B>>>(uidx, iidx, out, 0);

    // layer 2: B -> A
    spmm_csr_kernel<1><<<nodeGrid, B>>>();
    gather_kernel<0><<<gatherGrid, B>>>(uidx, iidx, out, 0);

    // layer 3: A -> B
    spmm_csr_kernel<0><<<nodeGrid, B>>>();
    gather_kernel<1><<<gatherGrid, B>>>(uidx, iidx, out, 0);
}

// round 3
// speedup vs baseline: 2.3239x; 1.5724x over previous
#include <cuda_runtime.h>
#include <cuda_fp16.h>

// Problem constants (fixed by the reference setup_inputs)
constexpr int N_USERS = 200000;
constexpr int N_ITEMS = 100000;
constexpr int N_NODES = N_USERS + N_ITEMS;   // 300000
constexpr int N_EDGES = 2000000;
constexpr int N_IDX   = 16384;
constexpr int DH      = 8;                   // 64 halves = 8 uint4 (16B) per row

constexpr int SCAN_B  = 1024;
constexpr int NBLK    = (N_NODES + SCAN_B - 1) / SCAN_B;  // 293

// Allocation-free scratch (__device__ globals)
__device__ uint4  g_bufA[(size_t)N_NODES * DH];   // 38.4 MB (fp16 rows)
__device__ uint4  g_bufB[(size_t)N_NODES * DH];   // 38.4 MB
__device__ int    g_cnt[N_NODES];
__device__ int    g_rowptr[N_NODES + 1];
__device__ int    g_cursor[N_NODES];
__device__ int    g_bsum[NBLK];
__device__ float2 g_edge[N_EDGES];                // {val, col-as-float-bits}, row-sorted

__device__ __forceinline__ uint4 pack8(const float* a) {
    uint4 r;
    half2 h0 = __floats2half2_rn(a[0], a[1]);
    half2 h1 = __floats2half2_rn(a[2], a[3]);
    half2 h2 = __floats2half2_rn(a[4], a[5]);
    half2 h3 = __floats2half2_rn(a[6], a[7]);
    r.x = *(const unsigned*)&h0; r.y = *(const unsigned*)&h1;
    r.z = *(const unsigned*)&h2; r.w = *(const unsigned*)&h3;
    return r;
}

__device__ __forceinline__ void unpack8(uint4 v, float* a) {
    float2 f0 = __half22float2(*(const half2*)&v.x);
    float2 f1 = __half22float2(*(const half2*)&v.y);
    float2 f2 = __half22float2(*(const half2*)&v.z);
    float2 f3 = __half22float2(*(const half2*)&v.w);
    a[0] = f0.x; a[1] = f0.y; a[2] = f1.x; a[3] = f1.y;
    a[4] = f2.x; a[5] = f2.y; a[6] = f3.x; a[7] = f3.y;
}

// ---------------------------------------------------------------------------
// init: bufA = fp16(concat(user_w, item_w)); zero histogram counters.
// One thread per uint4 (8 halves = 2 source float4s).
__global__ void init_kernel(const float4* __restrict__ uw,
                            const float4* __restrict__ iw) {
    int t = blockIdx.x * blockDim.x + threadIdx.x;
    if (t < N_NODES) g_cnt[t] = 0;
    if (t >= N_NODES * DH) return;
    const float4* src = (t < N_USERS * DH) ? uw : iw;
    int idx2 = (t < N_USERS * DH) ? (t * 2) : ((t - N_USERS * DH) * 2);
    float4 a = __ldg(src + idx2);
    float4 b = __ldg(src + idx2 + 1);
    float f[8] = {a.x, a.y, a.z, a.w, b.x, b.y, b.z, b.w};
    g_bufA[t] = pack8(f);
}

// histogram of edge rows
__global__ void hist_kernel(const int* __restrict__ rows) {
    int e = blockIdx.x * blockDim.x + threadIdx.x;
    if (e >= N_EDGES) return;
    atomicAdd(&g_cnt[__ldg(rows + e)], 1);
}

// 3-kernel exclusive scan over g_cnt -> g_rowptr (+ g_cursor copy)
__global__ void scan_blocks_kernel() {
    __shared__ int s[SCAN_B];
    int i = blockIdx.x * SCAN_B + threadIdx.x;
    int v = (i < N_NODES) ? g_cnt[i] : 0;
    s[threadIdx.x] = v;
    __syncthreads();
    #pragma unroll
    for (int off = 1; off < SCAN_B; off <<= 1) {
        int add = (threadIdx.x >= off) ? s[threadIdx.x - off] : 0;
        __syncthreads();
        s[threadIdx.x] += add;
        __syncthreads();
    }
    if (i < N_NODES) g_rowptr[i] = s[threadIdx.x] - v;
    if (threadIdx.x == SCAN_B - 1) g_bsum[blockIdx.x] = s[threadIdx.x];
}

__global__ void scan_bsums_kernel() {
    __shared__ int s[512];
    int v = (threadIdx.x < NBLK) ? g_bsum[threadIdx.x] : 0;
    s[threadIdx.x] = v;
    __syncthreads();
    #pragma unroll
    for (int off = 1; off < 512; off <<= 1) {
        int add = (threadIdx.x >= off) ? s[threadIdx.x - off] : 0;
        __syncthreads();
        s[threadIdx.x] += add;
        __syncthreads();
    }
    if (threadIdx.x < NBLK) g_bsum[threadIdx.x] = s[threadIdx.x] - v;
}

__global__ void scan_add_kernel() {
    int i = blockIdx.x * SCAN_B + threadIdx.x;
    if (i < N_NODES) {
        int r = g_rowptr[i] + g_bsum[blockIdx.x];
        g_rowptr[i] = r;
        g_cursor[i] = r;
    }
    if (i == 0) g_rowptr[N_NODES] = N_EDGES;
}

// scatter edges into row-sorted packed array
__global__ void scatter_kernel(const float* __restrict__ vals,
                               const int*   __restrict__ rows,
                               const int*   __restrict__ cols) {
    int e = blockIdx.x * blockDim.x + threadIdx.x;
    if (e >= N_EDGES) return;
    int r   = __ldg(rows + e);
    int pos = atomicAdd(&g_cursor[r], 1);
    g_edge[pos] = make_float2(__ldg(vals + e), __int_as_float(__ldg(cols + e)));
}

// ---------------------------------------------------------------------------
// CSR SpMM over fp16 rows with fp32 register accumulation.
// 8 threads per row; one 16B uint4 (8 halves) per thread per edge.
// DIR=0: cur=A, next=B.  DIR=1: cur=B, next=A.
template <int DIR>
__global__ void spmm_csr_kernel() {
    int t   = blockIdx.x * blockDim.x + threadIdx.x;
    int row = t >> 3;
    int c   = t & 7;
    if (row >= N_NODES) return;

    const uint4* __restrict__ cur = DIR ? g_bufB : g_bufA;
    uint4*       __restrict__ nxt = DIR ? g_bufA : g_bufB;

    int beg = __ldg(&g_rowptr[row]);
    int end = __ldg(&g_rowptr[row + 1]);

    float acc[8] = {0.f, 0.f, 0.f, 0.f, 0.f, 0.f, 0.f, 0.f};
    float x0[8], x1[8];
    int i = beg;
    for (; i + 1 < end; i += 2) {
        float2 ev0 = g_edge[i];
        float2 ev1 = g_edge[i + 1];
        uint4 p0 = __ldg(cur + (unsigned)__float_as_int(ev0.y) * DH + c);
        uint4 p1 = __ldg(cur + (unsigned)__float_as_int(ev1.y) * DH + c);
        unpack8(p0, x0);
        unpack8(p1, x1);
        #pragma unroll
        for (int k = 0; k < 8; k++) acc[k] += ev0.x * x0[k];
        #pragma unroll
        for (int k = 0; k < 8; k++) acc[k] += ev1.x * x1[k];
    }
    if (i < end) {
        float2 ev = g_edge[i];
        uint4 p = __ldg(cur + (unsigned)__float_as_int(ev.y) * DH + c);
        unpack8(p, x0);
        #pragma unroll
        for (int k = 0; k < 8; k++) acc[k] += ev.x * x0[k];
    }
    nxt[(unsigned)row * DH + c] = pack8(acc);
}

// Layer-0 gather: EXACT, from the fp32 weight tables. Overwrites out = 0.25*w.
__global__ void gather0_kernel(const float4* __restrict__ uw,
                               const float4* __restrict__ iw,
                               const int* __restrict__ uidx,
                               const int* __restrict__ iidx,
                               float4* __restrict__ out) {
    int t = blockIdx.x * blockDim.x + threadIdx.x;
    if (t >= 2 * N_IDX * 16) return;
    int row = t >> 4;
    int c   = t & 15;
    const float4* src;
    int node;
    if (row < N_IDX) { src = uw; node = __ldg(uidx + row); }
    else             { src = iw; node = __ldg(iidx + (row - N_IDX)); }
    float4 x = __ldg(src + (unsigned)node * 16 + c);
    out[t] = make_float4(0.25f * x.x, 0.25f * x.y, 0.25f * x.z, 0.25f * x.w);
}

// Layer 1..3 gathers: accumulate 0.25 * fp16-buf[sampled rows] into out.
// 8 threads per sampled row; each handles 8 floats (2 output float4s).
template <int W>
__global__ void gather_kernel(const int* __restrict__ uidx,
                              const int* __restrict__ iidx,
                              float4* __restrict__ out) {
    int t = blockIdx.x * blockDim.x + threadIdx.x;
    if (t >= 2 * N_IDX * DH) return;
    int row = t >> 3;
    int c   = t & 7;
    int node = (row < N_IDX) ? __ldg(uidx + row)
                             : (N_USERS + __ldg(iidx + (row - N_IDX)));
    const uint4* __restrict__ buf = W ? g_bufB : g_bufA;
    float x[8];
    unpack8(__ldg(buf + (unsigned)node * DH + c), x);
    float4* o = out + (unsigned)row * 16 + c * 2;
    float4 p0 = o[0], p1 = o[1];
    o[0] = make_float4(p0.x + 0.25f * x[0], p0.y + 0.25f * x[1],
                       p0.z + 0.25f * x[2], p0.w + 0.25f * x[3]);
    o[1] = make_float4(p1.x + 0.25f * x[4], p1.y + 0.25f * x[5],
                       p1.z + 0.25f * x[6], p1.w + 0.25f * x[7]);
}

extern "C" void kernel_launch(void* const* d_in, const int* in_sizes, int n_in,
                              void* d_out, int out_size) {
    const float4* uw   = (const float4*)d_in[0];
    const float4* iw   = (const float4*)d_in[1];
    const float*  vals = (const float*)d_in[2];
    const int*    rows = (const int*)d_in[3];
    const int*    cols = (const int*)d_in[4];
    const int*    uidx = (const int*)d_in[5];
    const int*    iidx = (const int*)d_in[6];
    float4*       out  = (float4*)d_out;

    const int B = 256;
    const int nodeGrid   = (N_NODES * DH + B - 1) / B;       // 9375
    const int edgeGrid   = (N_EDGES + B - 1) / B;            // 7813
    const int gather0Grid = (2 * N_IDX * 16 + B - 1) / B;    // 2048
    const int gatherGrid = (2 * N_IDX * DH + B - 1) / B;     // 1024

    // layer 0 + CSR build
    init_kernel<<<nodeGrid, B>>>(uw, iw);
    hist_kernel<<<edgeGrid, B>>>(rows);
    gather0_kernel<<<gather0Grid, B>>>(uw, iw, uidx, iidx, out);
    scan_blocks_kernel<<<NBLK, SCAN_B>>>();
    scan_bsums_kernel<<<1, 512>>>();
    scan_add_kernel<<<NBLK, SCAN_B>>>();
    scatter_kernel<<<edgeGrid, B>>>(vals, rows, cols);

    // layer 1: A -> B
    spmm_csr_kernel<0><<<nodeGrid, B>>>();
    gather_kernel<1><<<gatherGrid, B>>>(uidx, iidx, out);

    // layer 2: B -> A
    spmm_csr_kernel<1><<<nodeGrid, B>>>();
    gather_kernel<0><<<gatherGrid, B>>>(uidx, iidx, out);

    // layer 3: A -> B
    spmm_csr_kernel<0><<<nodeGrid, B>>>();
    gather_kernel<1><<<gatherGrid, B>>>(uidx, iidx, out);
}

// round 4
// speedup vs baseline: 2.5083x; 1.0793x over previous
#include <cuda_runtime.h>
#include <cuda_fp16.h>

// Problem constants (fixed by the reference setup_inputs)
constexpr int N_USERS = 200000;
constexpr int N_ITEMS = 100000;
constexpr int N_NODES = N_USERS + N_ITEMS;   // 300000
constexpr int N_EDGES = 2000000;
constexpr int N_IDX   = 16384;
constexpr int DH      = 8;                   // 64 halves = 8 uint4 (16B) per row
constexpr int MAX_SEL = 2 * N_IDX;           // upper bound on unique sampled nodes

constexpr int SCAN_B  = 1024;
constexpr int NBLK    = (N_NODES + SCAN_B - 1) / SCAN_B;  // 293

// Allocation-free scratch (__device__ globals)
__device__ uint4  g_bufA[(size_t)N_NODES * DH];   // 38.4 MB (fp16 rows)
__device__ uint4  g_bufB[(size_t)N_NODES * DH];   // 38.4 MB
__device__ int    g_cnt[N_NODES];
__device__ int    g_rowptr[N_NODES + 1];
__device__ int    g_cursor[N_NODES];
__device__ int    g_bsum[NBLK];
__device__ float2 g_edge[N_EDGES];                // {val, col-as-float-bits}, row-sorted
__device__ int    g_flag[N_NODES];
__device__ int    g_sel[MAX_SEL];
__device__ int    g_nsel;

__device__ __forceinline__ uint4 pack8(const float* a) {
    uint4 r;
    half2 h0 = __floats2half2_rn(a[0], a[1]);
    half2 h1 = __floats2half2_rn(a[2], a[3]);
    half2 h2 = __floats2half2_rn(a[4], a[5]);
    half2 h3 = __floats2half2_rn(a[6], a[7]);
    r.x = *(const unsigned*)&h0; r.y = *(const unsigned*)&h1;
    r.z = *(const unsigned*)&h2; r.w = *(const unsigned*)&h3;
    return r;
}

__device__ __forceinline__ void unpack8(uint4 v, float* a) {
    float2 f0 = __half22float2(*(const half2*)&v.x);
    float2 f1 = __half22float2(*(const half2*)&v.y);
    float2 f2 = __half22float2(*(const half2*)&v.z);
    float2 f3 = __half22float2(*(const half2*)&v.w);
    a[0] = f0.x; a[1] = f0.y; a[2] = f1.x; a[3] = f1.y;
    a[4] = f2.x; a[5] = f2.y; a[6] = f3.x; a[7] = f3.y;
}

// ---------------------------------------------------------------------------
// init: bufA = fp16(concat(user_w, item_w)); zero counters/flags.
__global__ void init_kernel(const float4* __restrict__ uw,
                            const float4* __restrict__ iw) {
    int t = blockIdx.x * blockDim.x + threadIdx.x;
    if (t < N_NODES) { g_cnt[t] = 0; g_flag[t] = 0; }
    if (t == 0) g_nsel = 0;
    if (t >= N_NODES * DH) return;
    const float4* src = (t < N_USERS * DH) ? uw : iw;
    int idx2 = (t < N_USERS * DH) ? (t * 2) : ((t - N_USERS * DH) * 2);
    float4 a = __ldg(src + idx2);
    float4 b = __ldg(src + idx2 + 1);
    float f[8] = {a.x, a.y, a.z, a.w, b.x, b.y, b.z, b.w};
    g_bufA[t] = pack8(f);
}

// mark sampled nodes + compact unique list (order irrelevant)
__global__ void mark_kernel(const int* __restrict__ uidx,
                            const int* __restrict__ iidx) {
    int t = blockIdx.x * blockDim.x + threadIdx.x;
    if (t >= 2 * N_IDX) return;
    int node = (t < N_IDX) ? __ldg(uidx + t) : (N_USERS + __ldg(iidx + (t - N_IDX)));
    if (atomicExch(&g_flag[node], 1) == 0) {
        int pos = atomicAdd(&g_nsel, 1);
        g_sel[pos] = node;
    }
}

// histogram of edge rows
__global__ void hist_kernel(const int* __restrict__ rows) {
    int e = blockIdx.x * blockDim.x + threadIdx.x;
    if (e >= N_EDGES) return;
    atomicAdd(&g_cnt[__ldg(rows + e)], 1);
}

// 3-kernel exclusive scan over g_cnt -> g_rowptr (+ g_cursor copy)
__global__ void scan_blocks_kernel() {
    __shared__ int s[SCAN_B];
    int i = blockIdx.x * SCAN_B + threadIdx.x;
    int v = (i < N_NODES) ? g_cnt[i] : 0;
    s[threadIdx.x] = v;
    __syncthreads();
    #pragma unroll
    for (int off = 1; off < SCAN_B; off <<= 1) {
        int add = (threadIdx.x >= off) ? s[threadIdx.x - off] : 0;
        __syncthreads();
        s[threadIdx.x] += add;
        __syncthreads();
    }
    if (i < N_NODES) g_rowptr[i] = s[threadIdx.x] - v;
    if (threadIdx.x == SCAN_B - 1) g_bsum[blockIdx.x] = s[threadIdx.x];
}

__global__ void scan_bsums_kernel() {
    __shared__ int s[512];
    int v = (threadIdx.x < NBLK) ? g_bsum[threadIdx.x] : 0;
    s[threadIdx.x] = v;
    __syncthreads();
    #pragma unroll
    for (int off = 1; off < 512; off <<= 1) {
        int add = (threadIdx.x >= off) ? s[threadIdx.x - off] : 0;
        __syncthreads();
        s[threadIdx.x] += add;
        __syncthreads();
    }
    if (threadIdx.x < NBLK) g_bsum[threadIdx.x] = s[threadIdx.x] - v;
}

__global__ void scan_add_kernel() {
    int i = blockIdx.x * SCAN_B + threadIdx.x;
    if (i < N_NODES) {
        int r = g_rowptr[i] + g_bsum[blockIdx.x];
        g_rowptr[i] = r;
        g_cursor[i] = r;
    }
    if (i == 0) g_rowptr[N_NODES] = N_EDGES;
}

// scatter edges into row-sorted packed array
__global__ void scatter_kernel(const float* __restrict__ vals,
                               const int*   __restrict__ rows,
                               const int*   __restrict__ cols) {
    int e = blockIdx.x * blockDim.x + threadIdx.x;
    if (e >= N_EDGES) return;
    int r   = __ldg(rows + e);
    int pos = atomicAdd(&g_cursor[r], 1);
    g_edge[pos] = make_float2(__ldg(vals + e), __int_as_float(__ldg(cols + e)));
}

// ---------------------------------------------------------------------------
// Row body: shuffle-cooperative CSR SpMM. 8 threads per row (c = lane&7).
// One coalesced 64B edge load per 8-edge chunk; {val,col} broadcast via shfl;
// all 8 gathers of the chunk independent and in flight simultaneously.
// Padding lanes use v=0/col=0 (hot L1 line, branchless).
__device__ __forceinline__ void spmm_row(const uint4* __restrict__ cur,
                                         uint4* __restrict__ nxt,
                                         int row, int c, bool do_store) {
    int beg = __ldg(&g_rowptr[row]);
    int end = __ldg(&g_rowptr[row + 1]);

    float acc[8] = {0.f, 0.f, 0.f, 0.f, 0.f, 0.f, 0.f, 0.f};
    for (int base = beg; base < end; base += 8) {
        int rem = end - base;
        float2 ev = (c < rem) ? __ldg((const float2*)g_edge + base + c)
                              : make_float2(0.f, __int_as_float(0));
        #pragma unroll
        for (int k = 0; k < 8; k++) {
            float v   = __shfl_sync(0xffffffffu, ev.x, k, 8);
            int   col = __float_as_int(__shfl_sync(0xffffffffu, ev.y, k, 8));
            float x[8];
            unpack8(__ldg(cur + (unsigned)col * DH + c), x);
            #pragma unroll
            for (int j = 0; j < 8; j++) acc[j] += v * x[j];
        }
    }
    if (do_store) nxt[(unsigned)row * DH + c] = pack8(acc);
}

// Full SpMM over all rows. DIR=0: A->B, DIR=1: B->A.
template <int DIR>
__global__ void spmm_csr_kernel() {
    int t   = blockIdx.x * blockDim.x + threadIdx.x;
    int row = t >> 3;
    int c   = t & 7;
    // grid sized exactly: N_NODES*8 threads, no partial warps
    const uint4* __restrict__ cur = DIR ? g_bufB : g_bufA;
    uint4*       __restrict__ nxt = DIR ? g_bufA : g_bufB;
    spmm_row(cur, nxt, row, c, true);
}

// Selective SpMM over the compacted sampled-node list (layer 3 only).
// All lanes stay active (clamped row) so width-8 shfl masks are uniform.
template <int DIR>
__global__ void spmm_sel_kernel() {
    int t    = blockIdx.x * blockDim.x + threadIdx.x;
    int ridx = t >> 3;
    int c    = t & 7;
    int nsel = g_nsel;
    bool live = ridx < nsel;
    int row  = g_sel[live ? ridx : 0];
    const uint4* __restrict__ cur = DIR ? g_bufB : g_bufA;
    uint4*       __restrict__ nxt = DIR ? g_bufA : g_bufB;
    spmm_row(cur, nxt, row, c, live);
}

// Layer-0 gather: EXACT, from the fp32 weight tables. Overwrites out = 0.25*w.
__global__ void gather0_kernel(const float4* __restrict__ uw,
                               const float4* __restrict__ iw,
                               const int* __restrict__ uidx,
                               const int* __restrict__ iidx,
                               float4* __restrict__ out) {
    int t = blockIdx.x * blockDim.x + threadIdx.x;
    if (t >= 2 * N_IDX * 16) return;
    int row = t >> 4;
    int c   = t & 15;
    const float4* src;
    int node;
    if (row < N_IDX) { src = uw; node = __ldg(uidx + row); }
    else             { src = iw; node = __ldg(iidx + (row - N_IDX)); }
    float4 x = __ldg(src + (unsigned)node * 16 + c);
    out[t] = make_float4(0.25f * x.x, 0.25f * x.y, 0.25f * x.z, 0.25f * x.w);
}

// Layer 1..3 gathers: accumulate 0.25 * fp16-buf[sampled rows] into out.
template <int W>
__global__ void gather_kernel(const int* __restrict__ uidx,
                              const int* __restrict__ iidx,
                              float4* __restrict__ out) {
    int t = blockIdx.x * blockDim.x + threadIdx.x;
    if (t >= 2 * N_IDX * DH) return;
    int row = t >> 3;
    int c   = t & 7;
    int node = (row < N_IDX) ? __ldg(uidx + row)
                             : (N_USERS + __ldg(iidx + (row - N_IDX)));
    const uint4* __restrict__ buf = W ? g_bufB : g_bufA;
    float x[8];
    unpack8(__ldg(buf + (unsigned)node * DH + c), x);
    float4* o = out + (unsigned)row * 16 + c * 2;
    float4 p0 = o[0], p1 = o[1];
    o[0] = make_float4(p0.x + 0.25f * x[0], p0.y + 0.25f * x[1],
                       p0.z + 0.25f * x[2], p0.w + 0.25f * x[3]);
    o[1] = make_float4(p1.x + 0.25f * x[4], p1.y + 0.25f * x[5],
                       p1.z + 0.25f * x[6], p1.w + 0.25f * x[7]);
}

extern "C" void kernel_launch(void* const* d_in, const int* in_sizes, int n_in,
                              void* d_out, int out_size) {
    const float4* uw   = (const float4*)d_in[0];
    const float4* iw   = (const float4*)d_in[1];
    const float*  vals = (const float*)d_in[2];
    const int*    rows = (const int*)d_in[3];
    const int*    cols = (const int*)d_in[4];
    const int*    uidx = (const int*)d_in[5];
    const int*    iidx = (const int*)d_in[6];
    float4*       out  = (float4*)d_out;

    const int B = 256;
    const int nodeGrid    = (N_NODES * DH + B - 1) / B;      // 9375 (exact: 2.4M/256)
    const int edgeGrid    = (N_EDGES + B - 1) / B;           // 7813
    const int gather0Grid = (2 * N_IDX * 16 + B - 1) / B;    // 2048
    const int gatherGrid  = (2 * N_IDX * DH + B - 1) / B;    // 1024
    const int markGrid    = (2 * N_IDX + B - 1) / B;         // 128
    const int selGrid     = (MAX_SEL * 8 + B - 1) / B;       // 1024

    // layer 0 + CSR build
    init_kernel<<<nodeGrid, B>>>(uw, iw);
    mark_kernel<<<markGrid, B>>>(uidx, iidx);
    hist_kernel<<<edgeGrid, B>>>(rows);
    gather0_kernel<<<gather0Grid, B>>>(uw, iw, uidx, iidx, out);
    scan_blocks_kernel<<<NBLK, SCAN_B>>>();
    scan_bsums_kernel<<<1, 512>>>();
    scan_add_kernel<<<NBLK, SCAN_B>>>();
    scatter_kernel<<<edgeGrid, B>>>(vals, rows, cols);

    // layer 1: A -> B (all rows)
    spmm_csr_kernel<0><<<nodeGrid, B>>>();
    gather_kernel<1><<<gatherGrid, B>>>(uidx, iidx, out);

    // layer 2: B -> A (all rows)
    spmm_csr_kernel<1><<<nodeGrid, B>>>();
    gather_kernel<0><<<gatherGrid, B>>>(uidx, iidx, out);

    // layer 3: A -> B, only sampled rows
    spmm_sel_kernel<0><<<selGrid, B>>>();
    gather_kernel<1><<<gatherGrid, B>>>(uidx, iidx, out);
}

// round 5
// speedup vs baseline: 3.3600x; 1.3395x over previous
#include <cuda_runtime.h>
#include <cuda_fp16.h>

// Problem constants (fixed by the reference setup_inputs)
constexpr int N_USERS = 200000;
constexpr int N_ITEMS = 100000;
constexpr int N_NODES = N_USERS + N_ITEMS;   // 300000
constexpr int N_EDGES = 2000000;
constexpr int N_IDX   = 16384;
constexpr int DH      = 8;                   // 64 halves = 8 uint4 (16B) per row
constexpr int N_SEL   = 2 * N_IDX;           // sampled-node list (with dups)

constexpr int SCAN_B  = 1024;
constexpr int NBLK    = (N_NODES + SCAN_B - 1) / SCAN_B;  // 293

// Allocation-free scratch (__device__ globals; zero-initialized at load)
__device__ uint4  g_bufA[(size_t)N_NODES * DH];   // 38.4 MB (fp16 rows)
__device__ uint4  g_bufB[(size_t)N_NODES * DH];   // 38.4 MB
__device__ int    g_cnt[N_NODES];                 // invariant: zero at launch entry
__device__ int    g_rowptr[N_NODES + 1];
__device__ int    g_cursor[N_NODES];
__device__ int    g_bsum[NBLK];
__device__ float2 g_edge[N_EDGES];                // {val, col-as-float-bits}, row-sorted
__device__ int    g_sel[N_SEL];                   // sampled nodes (dups ok)

__device__ __forceinline__ uint4 pack8(const float* a) {
    uint4 r;
    half2 h0 = __floats2half2_rn(a[0], a[1]);
    half2 h1 = __floats2half2_rn(a[2], a[3]);
    half2 h2 = __floats2half2_rn(a[4], a[5]);
    half2 h3 = __floats2half2_rn(a[6], a[7]);
    r.x = *(const unsigned*)&h0; r.y = *(const unsigned*)&h1;
    r.z = *(const unsigned*)&h2; r.w = *(const unsigned*)&h3;
    return r;
}

__device__ __forceinline__ void unpack8(uint4 v, float* a) {
    float2 f0 = __half22float2(*(const half2*)&v.x);
    float2 f1 = __half22float2(*(const half2*)&v.y);
    float2 f2 = __half22float2(*(const half2*)&v.z);
    float2 f3 = __half22float2(*(const half2*)&v.w);
    a[0] = f0.x; a[1] = f0.y; a[2] = f1.x; a[3] = f1.y;
    a[4] = f2.x; a[5] = f2.y; a[6] = f3.x; a[7] = f3.y;
}

// ---------------------------------------------------------------------------
// prep: fuses (a) bufA = fp16(concat(uw, iw)); (b) edge-row histogram
// (g_cnt is zero on entry by invariant); (c) sel-list fill (dups allowed);
// (d) exact layer-0 output gather from fp32 weights.
__global__ void prep_kernel(const float4* __restrict__ uw,
                            const float4* __restrict__ iw,
                            const int* __restrict__ rows,
                            const int* __restrict__ uidx,
                            const int* __restrict__ iidx,
                            float4* __restrict__ out) {
    int t = blockIdx.x * blockDim.x + threadIdx.x;

    // (a) fp16 conversion of the embedding table
    if (t < N_NODES * DH) {
        const float4* src = (t < N_USERS * DH) ? uw : iw;
        int idx2 = (t < N_USERS * DH) ? (t * 2) : ((t - N_USERS * DH) * 2);
        float4 a = __ldg(src + idx2);
        float4 b = __ldg(src + idx2 + 1);
        float f[8] = {a.x, a.y, a.z, a.w, b.x, b.y, b.z, b.w};
        g_bufA[t] = pack8(f);
    }
    // (b) histogram
    if (t < N_EDGES) atomicAdd(&g_cnt[__ldg(rows + t)], 1);
    // (c) sel list
    if (t < N_SEL) {
        g_sel[t] = (t < N_IDX) ? __ldg(uidx + t)
                               : (N_USERS + __ldg(iidx + (t - N_IDX)));
    }
    // (d) layer-0 exact gather: out = 0.25 * w[sampled]
    if (t < N_SEL * 16) {
        int row = t >> 4;
        int c   = t & 15;
        const float4* src;
        int node;
        if (row < N_IDX) { src = uw; node = __ldg(uidx + row); }
        else             { src = iw; node = __ldg(iidx + (row - N_IDX)); }
        float4 x = __ldg(src + (unsigned)node * 16 + c);
        out[t] = make_float4(0.25f * x.x, 0.25f * x.y, 0.25f * x.z, 0.25f * x.w);
    }
}

// ---------------------------------------------------------------------------
// shfl-based block scans (exclusive) over g_cnt -> g_rowptr.
// scan_blocks also RESETS g_cnt to 0 (launch invariant for next call).
__global__ void scan_blocks_kernel() {
    __shared__ int wsum[32];
    int i = blockIdx.x * SCAN_B + threadIdx.x;
    int v = (i < N_NODES) ? g_cnt[i] : 0;
    if (i < N_NODES) g_cnt[i] = 0;      // restore invariant
    int lane = threadIdx.x & 31, wid = threadIdx.x >> 5;
    int s = v;
    #pragma unroll
    for (int off = 1; off < 32; off <<= 1) {
        int n = __shfl_up_sync(0xffffffffu, s, off);
        if (lane >= off) s += n;
    }
    if (lane == 31) wsum[wid] = s;
    __syncthreads();
    if (wid == 0) {
        int ws = wsum[lane];
        #pragma unroll
        for (int off = 1; off < 32; off <<= 1) {
            int n = __shfl_up_sync(0xffffffffu, ws, off);
            if (lane >= off) ws += n;
        }
        wsum[lane] = ws;
    }
    __syncthreads();
    int incl = s + ((wid > 0) ? wsum[wid - 1] : 0);
    if (i < N_NODES) g_rowptr[i] = incl - v;            // exclusive within block
    if (threadIdx.x == SCAN_B - 1) g_bsum[blockIdx.x] = incl;
}

__global__ void scan_bsums_kernel() {   // 512 threads, NBLK=293
    __shared__ int wsum[16];
    int lane = threadIdx.x & 31, wid = threadIdx.x >> 5;
    int v = (threadIdx.x < NBLK) ? g_bsum[threadIdx.x] : 0;
    int s = v;
    #pragma unroll
    for (int off = 1; off < 32; off <<= 1) {
        int n = __shfl_up_sync(0xffffffffu, s, off);
        if (lane >= off) s += n;
    }
    if (lane == 31) wsum[wid] = s;
    __syncthreads();
    if (wid == 0 && lane < 16) {
        int ws = wsum[lane];
        #pragma unroll
        for (int off = 1; off < 16; off <<= 1) {
            int n = __shfl_up_sync(0x0000ffffu, ws, off);
            if (lane >= off) ws += n;
        }
        wsum[lane] = ws;
    }
    __syncthreads();
    int incl = s + ((wid > 0) ? wsum[wid - 1] : 0);
    if (threadIdx.x < NBLK) g_bsum[threadIdx.x] = incl - v;   // exclusive
}

__global__ void scan_add_kernel() {
    int i = blockIdx.x * SCAN_B + threadIdx.x;
    if (i < N_NODES) {
        int r = g_rowptr[i] + g_bsum[blockIdx.x];
        g_rowptr[i] = r;
        g_cursor[i] = r;
    }
    if (i == 0) g_rowptr[N_NODES] = N_EDGES;
}

// scatter edges into row-sorted packed array
__global__ void scatter_kernel(const float* __restrict__ vals,
                               const int*   __restrict__ rows,
                               const int*   __restrict__ cols) {
    int e = blockIdx.x * blockDim.x + threadIdx.x;
    if (e >= N_EDGES) return;
    int r   = __ldg(rows + e);
    int pos = atomicAdd(&g_cursor[r], 1);
    g_edge[pos] = make_float2(__ldg(vals + e), __int_as_float(__ldg(cols + e)));
}

// ---------------------------------------------------------------------------
// Row body: direct per-thread CSR loop, chunk-4 with zero-padding.
// 8 threads per row (c = lane&7). Per chunk: 4 independent edge loads
// (broadcast across the 8 lanes -> 1 sector each), then 4 independent
// gathers in flight. Padded slots use v=0/col=0 (hot L1 line, branchless).
__device__ __forceinline__ void spmm_row(const uint4* __restrict__ cur,
                                         uint4* __restrict__ nxt,
                                         int row, int c) {
    int beg = __ldg(&g_rowptr[row]);
    int end = __ldg(&g_rowptr[row + 1]);

    float acc[8] = {0.f, 0.f, 0.f, 0.f, 0.f, 0.f, 0.f, 0.f};
    for (int base = beg; base < end; base += 4) {
        float2 ev[4];
        #pragma unroll
        for (int k = 0; k < 4; k++) {
            int idx = base + k;
            ev[k] = (idx < end) ? __ldg((const float2*)g_edge + idx)
                                : make_float2(0.f, __int_as_float(0));
        }
        uint4 p[4];
        #pragma unroll
        for (int k = 0; k < 4; k++)
            p[k] = __ldg(cur + (unsigned)__float_as_int(ev[k].y) * DH + c);
        #pragma unroll
        for (int k = 0; k < 4; k++) {
            float x[8];
            unpack8(p[k], x);
            #pragma unroll
            for (int j = 0; j < 8; j++) acc[j] += ev[k].x * x[j];
        }
    }
    nxt[(unsigned)row * DH + c] = pack8(acc);
}

// Fused gather tail: out += 0.25 * buf16[sampled]  (8 threads/sampled row)
__device__ __forceinline__ void gather_body(const uint4* __restrict__ buf,
                                            float4* __restrict__ out, int t) {
    int row = t >> 3;
    int c   = t & 7;
    int node = g_sel[row];
    float x[8];
    unpack8(__ldg(buf + (unsigned)node * DH + c), x);
    float4* o = out + (unsigned)row * 16 + c * 2;
    float4 p0 = o[0], p1 = o[1];
    o[0] = make_float4(p0.x + 0.25f * x[0], p0.y + 0.25f * x[1],
                       p0.z + 0.25f * x[2], p0.w + 0.25f * x[3]);
    o[1] = make_float4(p1.x + 0.25f * x[4], p1.y + 0.25f * x[5],
                       p1.z + 0.25f * x[6], p1.w + 0.25f * x[7]);
}

constexpr int SPMM_BLOCKS   = (N_NODES * DH) / 256;          // 9375
constexpr int GATHER_BLOCKS = (N_SEL * DH) / 256;            // 1024
constexpr int SEL_BLOCKS    = (N_SEL * DH) / 256;            // 1024

// Full SpMM over all rows. DIR=0: A->B, DIR=1: B->A.
// GPREV: -1 = no fused gather; else gather from buf GPREV (0=A,1=B) into out.
template <int DIR, int GPREV>
__global__ void spmm_csr_kernel(float4* __restrict__ out) {
    const uint4* __restrict__ cur = DIR ? g_bufB : g_bufA;
    uint4*       __restrict__ nxt = DIR ? g_bufA : g_bufB;
    int b = blockIdx.x;
    if (b < SPMM_BLOCKS) {
        int t = b * blockDim.x + threadIdx.x;
        spmm_row(cur, nxt, t >> 3, t & 7);
    } else if (GPREV >= 0) {
        int t = (b - SPMM_BLOCKS) * blockDim.x + threadIdx.x;
        gather_body(GPREV ? g_bufB : g_bufA, out, t);
    }
}

// Selective SpMM over sampled rows (dups benign: identical values written).
// Fused gather of the previous layer (GPREV buffer) in tail blocks.
template <int DIR, int GPREV>
__global__ void spmm_sel_kernel(float4* __restrict__ out) {
    const uint4* __restrict__ cur = DIR ? g_bufB : g_bufA;
    uint4*       __restrict__ nxt = DIR ? g_bufA : g_bufB;
    int b = blockIdx.x;
    if (b < SEL_BLOCKS) {
        int t = b * blockDim.x + threadIdx.x;
        spmm_row(cur, nxt, g_sel[t >> 3], t & 7);
    } else {
        int t = (b - SEL_BLOCKS) * blockDim.x + threadIdx.x;
        gather_body(GPREV ? g_bufB : g_bufA, out, t);
    }
}

// Final standalone gather (layer 3 result)
template <int W>
__global__ void gather_kernel(float4* __restrict__ out) {
    int t = blockIdx.x * blockDim.x + threadIdx.x;
    gather_body(W ? g_bufB : g_bufA, out, t);
}

extern "C" void kernel_launch(void* const* d_in, const int* in_sizes, int n_in,
                              void* d_out, int out_size) {
    const float4* uw   = (const float4*)d_in[0];
    const float4* iw   = (const float4*)d_in[1];
    const float*  vals = (const float*)d_in[2];
    const int*    rows = (const int*)d_in[3];
    const int*    cols = (const int*)d_in[4];
    const int*    uidx = (const int*)d_in[5];
    const int*    iidx = (const int*)d_in[6];
    float4*       out  = (float4*)d_out;

    const int B = 256;
    const int prepGrid = (N_NODES * DH + B - 1) / B;   // 9375 (covers all fused jobs)
    const int edgeGrid = (N_EDGES + B - 1) / B;        // 7813

    // prologue: fp16 convert + histogram + sel list + exact layer-0 gather
    prep_kernel<<<prepGrid, B>>>(uw, iw, rows, uidx, iidx, out);
    scan_blocks_kernel<<<NBLK, SCAN_B>>>();
    scan_bsums_kernel<<<1, 512>>>();
    scan_add_kernel<<<NBLK, SCAN_B>>>();
    scatter_kernel<<<edgeGrid, B>>>(vals, rows, cols);

    // layer 1: A -> B (all rows)
    spmm_csr_kernel<0, -1><<<SPMM_BLOCKS, B>>>(out);
    // layer 2: B -> A (all rows) + fused gather of layer-1 (bufB)
    spmm_csr_kernel<1, 1><<<SPMM_BLOCKS + GATHER_BLOCKS, B>>>(out);
    // layer 3: A -> B (sampled rows) + fused gather of layer-2 (bufA)
    spmm_sel_kernel<0, 0><<<SEL_BLOCKS + GATHER_BLOCKS, B>>>(out);
    // final gather of layer-3 (bufB)
    gather_kernel<1><<<GATHER_BLOCKS, B>>>(out);
}